// round 2
// baseline (speedup 1.0000x reference)
#include <cuda_runtime.h>

#define T_STEPS 750
#define B_TOT   1024
#define HID     100
#define KDIM    104      // 100 recurrent + 4 input-drive rows
#define BTILE   8
#define NTHREADS 128
#define ALPHA   0.01f
#define NSTD    0.1f

__device__ __forceinline__ float tanh_fast(float x) {
    float y;
    asm("tanh.approx.f32 %0, %1;" : "=f"(y) : "f"(x));
    return y;
}
__device__ __forceinline__ unsigned long long pack2(float x) {
    unsigned long long r;
    asm("mov.b64 %0, {%1, %1};" : "=l"(r) : "f"(x));
    return r;
}
__device__ __forceinline__ void ffma2(unsigned long long& d,
                                      unsigned long long a,
                                      unsigned long long b) {
    asm("fma.rn.f32x2 %0, %1, %2, %0;" : "+l"(d) : "l"(a), "l"(b));
}
__device__ __forceinline__ float2 unpack2(unsigned long long v) {
    float2 f;
    asm("mov.b64 {%0, %1}, %2;" : "=f"(f.x), "=f"(f.y) : "l"(v));
    return f;
}

// One RNN step: write R = [tanh(x); u_t] to shared, GEMM y = Jreg . R,
// prefetch next step's noise/u, update x in registers.
__device__ __forceinline__ void rnn_step(
    int tcur, int i, int b0,
    float (&x)[BTILE], const float (&Jreg)[KDIM], float ci,
    const float (&ncur)[BTILE], float ucur,
    float (&nnext)[BTILE], float& unext,
    float (&R)[KDIM][BTILE],
    const float* __restrict__ noise,
    const float* __restrict__ input_seq)
{
    // Phase 1: publish r = tanh(x) rows (i < 100) and u rows (rows 100..103)
    if (i < HID) {
        float4 r0, r1;
        r0.x = tanh_fast(x[0]); r0.y = tanh_fast(x[1]);
        r0.z = tanh_fast(x[2]); r0.w = tanh_fast(x[3]);
        r1.x = tanh_fast(x[4]); r1.y = tanh_fast(x[5]);
        r1.z = tanh_fast(x[6]); r1.w = tanh_fast(x[7]);
        *(float4*)&R[i][0] = r0;
        *(float4*)&R[i][4] = r1;
    }
    if (i < 32) R[HID + (i & 3)][i >> 2] = ucur;   // lane -> (b = i>>2, c = i&3)
    __syncthreads();

    // Prefetch next step's noise + input (one full step ahead of use)
    const int tn = (tcur + 1 < T_STEPS) ? (tcur + 1) : tcur;
    {
        const float* np = noise + ((size_t)tn * B_TOT + b0) * HID + i;
#pragma unroll
        for (int b = 0; b < BTILE; b++)
            nnext[b] = (i < HID) ? np[b * HID] : 0.0f;
        if (i < 32)
            unext = input_seq[((size_t)tn * B_TOT + b0 + (i >> 2)) * 4 + (i & 3)];
    }

    // Phase 2: y[b] = sum_j Jreg[j] * R[j][b]   (8 accumulators as 4 f32x2)
    unsigned long long y01 = 0ull, y23 = 0ull, y45 = 0ull, y67 = 0ull;
#pragma unroll
    for (int j = 0; j < KDIM; j++) {
        ulonglong2 rlo = *(const ulonglong2*)&R[j][0];   // R[j][0..3]
        ulonglong2 rhi = *(const ulonglong2*)&R[j][4];   // R[j][4..7]
        unsigned long long jj = pack2(Jreg[j]);
        ffma2(y01, rlo.x, jj);
        ffma2(y23, rlo.y, jj);
        ffma2(y45, rhi.x, jj);
        ffma2(y67, rhi.y, jj);
    }
    __syncthreads();   // all reads of R done before next step overwrites it

    // Phase 3: x <- (1-a)x + a*y + a*c + (a*noise_std)*n   (registers only)
    float2 f01 = unpack2(y01), f23 = unpack2(y23);
    float2 f45 = unpack2(y45), f67 = unpack2(y67);
    float y[BTILE] = { f01.x, f01.y, f23.x, f23.y, f45.x, f45.y, f67.x, f67.y };
#pragma unroll
    for (int b = 0; b < BTILE; b++) {
        x[b] = fmaf(1.0f - ALPHA, x[b],
               fmaf(ALPHA, y[b],
               fmaf(ALPHA * NSTD, ncur[b], ci)));
    }
}

__global__ void __launch_bounds__(NTHREADS, 1)
rnn_kernel(const float* __restrict__ input_seq,
           const float* __restrict__ noise,
           const float* __restrict__ J_w,
           const float* __restrict__ Bmat,
           const float* __restrict__ c_x,
           const float* __restrict__ Wout_w,
           const float* __restrict__ Wout_b,
           float* __restrict__ out)
{
    __shared__ __align__(16) float R[KDIM][BTILE];
    __shared__ float warp_part[4][BTILE];   // per-warp partial sums (epilogue)

    const int i  = threadIdx.x;            // state row owned by this thread
    const int b0 = blockIdx.x * BTILE;     // batch slice base

    // Row i of [J ; Bmat^T] held permanently in registers (static indexing).
    float Jreg[KDIM];
#pragma unroll
    for (int j = 0; j < KDIM; j++) {
        float v = 0.0f;
        if (i < HID)
            v = (j < HID) ? J_w[i * HID + j] : Bmat[(j - HID) * HID + i];
        Jreg[j] = v;
    }
    const float ci = (i < HID) ? (ALPHA * c_x[i]) : 0.0f;

    float x[BTILE];
#pragma unroll
    for (int b = 0; b < BTILE; b++) x[b] = 0.0f;

    // Preload t=0 noise + input into buffer A
    float nA[BTILE], nB[BTILE];
    float uA = 0.0f, uB = 0.0f;
    {
        const float* np = noise + (size_t)b0 * HID + i;
#pragma unroll
        for (int b = 0; b < BTILE; b++)
            nA[b] = (i < HID) ? np[b * HID] : 0.0f;
        if (i < 32)
            uA = input_seq[((size_t)b0 + (i >> 2)) * 4 + (i & 3)];
    }

    // Main scan, unrolled by 2 for register double-buffering of noise/input
    for (int t = 0; t < T_STEPS; t += 2) {
        rnn_step(t,     i, b0, x, Jreg, ci, nA, uA, nB, uB, R, noise, input_seq);
        rnn_step(t + 1, i, b0, x, Jreg, ci, nB, uB, nA, uA, R, noise, input_seq);
    }

    // Epilogue: out[b] = tanh(x_final[b]) . Wout + bias.
    // Deterministic reduction: butterfly shuffle within warp, then cross-warp
    // combine through shared memory (fixed order).
    {
        const float w = (i < HID) ? Wout_w[i] : 0.0f;
        float part[BTILE];
#pragma unroll
        for (int b = 0; b < BTILE; b++)
            part[b] = (i < HID) ? w * tanhf(x[b]) : 0.0f;
#pragma unroll
        for (int off = 16; off > 0; off >>= 1) {
#pragma unroll
            for (int b = 0; b < BTILE; b++)
                part[b] += __shfl_xor_sync(0xFFFFFFFFu, part[b], off);
        }
        const int warp = i >> 5;
        if ((i & 31) == 0) {
#pragma unroll
            for (int b = 0; b < BTILE; b++)
                warp_part[warp][b] = part[b];
        }
        __syncthreads();
        if (i < BTILE) {
            float s = warp_part[0][i] + warp_part[1][i]
                    + warp_part[2][i] + warp_part[3][i];
            out[b0 + i] = s + Wout_b[0];
        }
    }
}

extern "C" void kernel_launch(void* const* d_in, const int* in_sizes, int n_in,
                              void* d_out, int out_size)
{
    const float* input_seq = (const float*)d_in[0];  // [750,1024,4]
    const float* noise     = (const float*)d_in[1];  // [750,1024,100]
    const float* J_w       = (const float*)d_in[2];  // [100,100]
    const float* Bmat      = (const float*)d_in[3];  // [4,100]
    const float* c_x       = (const float*)d_in[4];  // [100]
    const float* Wout_w    = (const float*)d_in[5];  // [1,100]
    const float* Wout_b    = (const float*)d_in[6];  // [1]
    float* out = (float*)d_out;                      // [1024]

    rnn_kernel<<<B_TOT / BTILE, NTHREADS>>>(
        input_seq, noise, J_w, Bmat, c_x, Wout_w, Wout_b, out);
}

// round 5
// speedup vs baseline: 1.3591x; 1.3591x over previous
#include <cuda_runtime.h>

#define T_STEPS 750
#define B_TOT   1024
#define HID     100
#define KDIM    104      // 100 recurrent + 4 input-drive rows
#define BTILE   4
#define NTHREADS 128
#define NBLOCKS (B_TOT / BTILE)   // 256
#define ALPHA   0.01f
#define NSTD    0.1f

__device__ __forceinline__ float tanh_fast(float x) {
    float y;
    asm("tanh.approx.f32 %0, %1;" : "=f"(y) : "f"(x));
    return y;
}
__device__ __forceinline__ unsigned long long pack2(float x) {
    unsigned long long r;
    asm("mov.b64 %0, {%1, %1};" : "=l"(r) : "f"(x));
    return r;
}
__device__ __forceinline__ void ffma2(unsigned long long& d,
                                      unsigned long long a,
                                      unsigned long long b) {
    asm("fma.rn.f32x2 %0, %1, %2, %0;" : "+l"(d) : "l"(a), "l"(b));
}
__device__ __forceinline__ unsigned long long fadd2(unsigned long long a,
                                                    unsigned long long b) {
    unsigned long long r;
    asm("add.rn.f32x2 %0, %1, %2;" : "=l"(r) : "l"(a), "l"(b));
    return r;
}
__device__ __forceinline__ float2 unpack2(unsigned long long v) {
    float2 f;
    asm("mov.b64 {%0, %1}, %2;" : "=f"(f.x), "=f"(f.y) : "l"(v));
    return f;
}

// One RNN step: publish R = [tanh(x); u_t] to shared, y = Jreg . R,
// prefetch next step's noise/u, update x in registers.
__device__ __forceinline__ void rnn_step(
    int tcur, int i, int b0,
    float (&x)[BTILE], const float (&Jreg)[KDIM], float ci,
    const float (&ncur)[BTILE], float ucur,
    float (&nnext)[BTILE], float& unext,
    float (&R)[KDIM][BTILE],
    const float* __restrict__ noise,
    const float* __restrict__ input_seq)
{
    // Phase 1: r rows (i<100) + u rows (100..103, lanes 0..15: b=i>>2, c=i&3)
    if (i < HID) {
        float4 r0;
        r0.x = tanh_fast(x[0]); r0.y = tanh_fast(x[1]);
        r0.z = tanh_fast(x[2]); r0.w = tanh_fast(x[3]);
        *(float4*)&R[i][0] = r0;
    }
    if (i < 16) R[HID + (i & 3)][i >> 2] = ucur;
    __syncthreads();

    // Prefetch next step's noise + input (one full step ahead of use)
    const int tn = (tcur + 1 < T_STEPS) ? (tcur + 1) : tcur;
    {
        const float* np = noise + ((size_t)tn * B_TOT + b0) * HID + i;
#pragma unroll
        for (int b = 0; b < BTILE; b++)
            nnext[b] = (i < HID) ? np[b * HID] : 0.0f;
        if (i < 16)
            unext = input_seq[((size_t)tn * B_TOT + b0 + (i >> 2)) * 4 + (i & 3)];
    }

    // Phase 2: y[b] = sum_j Jreg[j] * R[j][b]
    // 4 packed accumulators (even/odd j) -> 2x slack on the lat-4 FMA chain.
    unsigned long long ya0 = 0ull, ya1 = 0ull, yb0 = 0ull, yb1 = 0ull;
#pragma unroll
    for (int j = 0; j < KDIM; j += 2) {
        ulonglong2 ra = *(const ulonglong2*)&R[j][0];       // R[j][0..3]
        ulonglong2 rb = *(const ulonglong2*)&R[j + 1][0];   // R[j+1][0..3]
        unsigned long long ja = pack2(Jreg[j]);
        unsigned long long jb = pack2(Jreg[j + 1]);
        ffma2(ya0, ra.x, ja);
        ffma2(ya1, ra.y, ja);
        ffma2(yb0, rb.x, jb);
        ffma2(yb1, rb.y, jb);
    }
    __syncthreads();   // all reads of R done before next step overwrites it

    unsigned long long y01 = fadd2(ya0, yb0);
    unsigned long long y23 = fadd2(ya1, yb1);

    // Phase 3: x <- (1-a)x + a*y + a*c + (a*noise_std)*n   (registers only)
    float2 f01 = unpack2(y01), f23 = unpack2(y23);
    float y[BTILE] = { f01.x, f01.y, f23.x, f23.y };
#pragma unroll
    for (int b = 0; b < BTILE; b++) {
        x[b] = fmaf(1.0f - ALPHA, x[b],
               fmaf(ALPHA, y[b],
               fmaf(ALPHA * NSTD, ncur[b], ci)));
    }
}

__global__ void __launch_bounds__(NTHREADS, 2)
rnn_kernel(const float* __restrict__ input_seq,
           const float* __restrict__ noise,
           const float* __restrict__ J_w,
           const float* __restrict__ Bmat,
           const float* __restrict__ c_x,
           const float* __restrict__ Wout_w,
           const float* __restrict__ Wout_b,
           float* __restrict__ out)
{
    __shared__ __align__(16) float R[KDIM][BTILE];
    __shared__ float warp_part[4][BTILE];   // per-warp partial sums (epilogue)

    const int i  = threadIdx.x;            // state row owned by this thread
    const int b0 = blockIdx.x * BTILE;     // batch slice base

    // Row i of [J ; Bmat^T] held permanently in registers (static indexing).
    float Jreg[KDIM];
#pragma unroll
    for (int j = 0; j < KDIM; j++) {
        float v = 0.0f;
        if (i < HID)
            v = (j < HID) ? J_w[i * HID + j] : Bmat[(j - HID) * HID + i];
        Jreg[j] = v;
    }
    const float ci = (i < HID) ? (ALPHA * c_x[i]) : 0.0f;

    float x[BTILE];
#pragma unroll
    for (int b = 0; b < BTILE; b++) x[b] = 0.0f;

    // Preload t=0 noise + input into buffer A
    float nA[BTILE], nB[BTILE];
    float uA = 0.0f, uB = 0.0f;
    {
        const float* np = noise + (size_t)b0 * HID + i;
#pragma unroll
        for (int b = 0; b < BTILE; b++)
            nA[b] = (i < HID) ? np[b * HID] : 0.0f;
        if (i < 16)
            uA = input_seq[((size_t)b0 + (i >> 2)) * 4 + (i & 3)];
    }

    // Main scan, unrolled by 2 for register double-buffering of noise/input
    for (int t = 0; t < T_STEPS; t += 2) {
        rnn_step(t,     i, b0, x, Jreg, ci, nA, uA, nB, uB, R, noise, input_seq);
        rnn_step(t + 1, i, b0, x, Jreg, ci, nB, uB, nA, uA, R, noise, input_seq);
    }

    // Epilogue: out[b] = tanh(x_final[b]) . Wout + bias.
    // Deterministic: butterfly shuffle within warp, fixed-order cross-warp sum.
    {
        const float w = (i < HID) ? Wout_w[i] : 0.0f;
        float part[BTILE];
#pragma unroll
        for (int b = 0; b < BTILE; b++)
            part[b] = (i < HID) ? w * tanhf(x[b]) : 0.0f;
#pragma unroll
        for (int off = 16; off > 0; off >>= 1) {
#pragma unroll
            for (int b = 0; b < BTILE; b++)
                part[b] += __shfl_xor_sync(0xFFFFFFFFu, part[b], off);
        }
        const int warp = i >> 5;
        if ((i & 31) == 0) {
#pragma unroll
            for (int b = 0; b < BTILE; b++)
                warp_part[warp][b] = part[b];
        }
        __syncthreads();
        if (i < BTILE) {
            float s = warp_part[0][i] + warp_part[1][i]
                    + warp_part[2][i] + warp_part[3][i];
            out[b0 + i] = s + Wout_b[0];
        }
    }
}

extern "C" void kernel_launch(void* const* d_in, const int* in_sizes, int n_in,
                              void* d_out, int out_size)
{
    const float* input_seq = (const float*)d_in[0];  // [750,1024,4]
    const float* noise     = (const float*)d_in[1];  // [750,1024,100]
    const float* J_w       = (const float*)d_in[2];  // [100,100]
    const float* Bmat      = (const float*)d_in[3];  // [4,100]
    const float* c_x       = (const float*)d_in[4];  // [100]
    const float* Wout_w    = (const float*)d_in[5];  // [1,100]
    const float* Wout_b    = (const float*)d_in[6];  // [1]
    float* out = (float*)d_out;                      // [1024]

    rnn_kernel<<<NBLOCKS, NTHREADS>>>(
        input_seq, noise, J_w, Bmat, c_x, Wout_w, Wout_b, out);
}